// round 3
// baseline (speedup 1.0000x reference)
#include <cuda_runtime.h>

typedef unsigned long long u64;

// ---------------------------------------------------------------------------
// Static device scratch (allowed: no runtime allocation).
// Projection tables padded to 12 floats/row (48B) so rows are 16B-aligned
// for LDG.128 gathers.
// ---------------------------------------------------------------------------
#define NS_MAX 100000
#define NT_MAX 100000
#define BB_MAX 10000

__device__ __align__(16) float g_Ps[NS_MAX * 12];
__device__ __align__(16) float g_Pt[NT_MAX * 12];
__device__ __align__(16) float g_Pu[BB_MAX * 12];

// ---------------------------------------------------------------------------
// Packed f32x2 helpers (Blackwell sm_103a). ptxas never auto-fuses these.
// ---------------------------------------------------------------------------
__device__ __forceinline__ u64 pk2(float lo, float hi) {
    u64 r; asm("mov.b64 %0, {%1, %2};" : "=l"(r) : "f"(lo), "f"(hi)); return r;
}
__device__ __forceinline__ void upk2(u64 v, float& lo, float& hi) {
    asm("mov.b64 {%0, %1}, %2;" : "=f"(lo), "=f"(hi) : "l"(v));
}
__device__ __forceinline__ u64 fma2(u64 a, u64 b, u64 c) {
    u64 d; asm("fma.rn.f32x2 %0, %1, %2, %3;" : "=l"(d) : "l"(a), "l"(b), "l"(c)); return d;
}
__device__ __forceinline__ u64 add2(u64 a, u64 b) {
    u64 d; asm("add.rn.f32x2 %0, %1, %2;" : "=l"(d) : "l"(a), "l"(b)); return d;
}

// ---------------------------------------------------------------------------
// Projection kernel: out[i][j] = bias[j] + sum_k x[i][k] * W1[row0+k][j]
// which selects the destination table (0=Ps, 1=Pt, 2=Pu).
// Tiny: <=100k rows, 50-100 FMA each.
// ---------------------------------------------------------------------------
__global__ void proj_kernel(const float* __restrict__ x, int n, int f,
                            const float* __restrict__ W1, int row0,
                            const float* __restrict__ bias, int which)
{
    float* out = (which == 0) ? g_Ps : (which == 1) ? g_Pt : g_Pu;
    __shared__ float sW[10][10];
    __shared__ float sB[10];
    int t = threadIdx.x;
    if (t < f * 10) sW[t / 10][t % 10] = W1[(row0 + t / 10) * 10 + (t % 10)];
    if (t < 10)     sB[t] = bias ? bias[t] : 0.0f;
    __syncthreads();

    int i = blockIdx.x * blockDim.x + t;
    if (i >= n) return;

    float acc[10];
#pragma unroll
    for (int j = 0; j < 10; j++) acc[j] = sB[j];
    for (int k = 0; k < f; k++) {
        float xv = __ldg(&x[i * f + k]);
#pragma unroll
        for (int j = 0; j < 10; j++) acc[j] = fmaf(xv, sW[k][j], acc[j]);
    }
#pragma unroll
    for (int j = 0; j < 10; j++) out[i * 12 + j] = acc[j];
}

// ---------------------------------------------------------------------------
// Fused per-edge kernel. 2 edges per thread (shares weight LDS, gives MLP).
//   mid = lrelu(Ps[src] + Pt[tgt] + Pu[be] + ea @ W1c)   (b1 folded into Pu)
//   out = mid @ W2 + b2
// All accumulation in packed f32x2 pairs (5 pairs = 10 features).
// ---------------------------------------------------------------------------
__device__ __forceinline__ void gather_base(int src, int tgt, int bb, u64 acc[5])
{
    const float* rs = g_Ps + src * 12;
    const float* rt = g_Pt + tgt * 12;
    const float* ru = g_Pu + bb * 12;
    ulonglong2 a0 = ((const ulonglong2*)rs)[0], a1 = ((const ulonglong2*)rs)[1];
    u64        a2 = ((const u64*)rs)[4];
    ulonglong2 b0 = ((const ulonglong2*)rt)[0], b1 = ((const ulonglong2*)rt)[1];
    u64        b2 = ((const u64*)rt)[4];
    ulonglong2 c0 = ((const ulonglong2*)ru)[0], c1 = ((const ulonglong2*)ru)[1];
    u64        c2 = ((const u64*)ru)[4];
    acc[0] = add2(add2(a0.x, b0.x), c0.x);
    acc[1] = add2(add2(a0.y, b0.y), c0.y);
    acc[2] = add2(add2(a1.x, b1.x), c1.x);
    acc[3] = add2(add2(a1.y, b1.y), c1.y);
    acc[4] = add2(add2(a2,   b2),   c2);
}

__device__ __forceinline__ void load_ea(const float* __restrict__ ea, int e, float a[10])
{
    const float2* p = (const float2*)ea + e * 5;
#pragma unroll
    for (int m = 0; m < 5; m++) { float2 v = p[m]; a[2 * m] = v.x; a[2 * m + 1] = v.y; }
}

__global__ __launch_bounds__(256) void edge_kernel(
    const int*   __restrict__ ei,   // [2, E]
    const float* __restrict__ ea,   // [E, 10]
    const int*   __restrict__ be,   // [E]
    const float* __restrict__ W1,   // [35, 10]
    const float* __restrict__ W2,   // [10, 10]
    const float* __restrict__ b2,   // [10]
    float*       __restrict__ out,  // [E, 10]
    int E)
{
    // Weights in smem, rows padded to 12 floats (48B) -> 16B-aligned LDS.128.
    __shared__ __align__(16) float sW1c[10][12];
    __shared__ __align__(16) float sW2s[10][12];
    int t = threadIdx.x;
    if (t < 120) {
        int k = t / 12, j = t % 12;
        sW1c[k][j] = (j < 10) ? W1[(15 + k) * 10 + j] : 0.0f;
        sW2s[k][j] = (j < 10) ? W2[k * 10 + j] : 0.0f;
    }
    __syncthreads();

    // b2 as 5 packed pairs, kept in registers.
    u64 b2p[5];
    {
        const float2* B2 = (const float2*)b2;
#pragma unroll
        for (int j = 0; j < 5; j++) { float2 v = B2[j]; b2p[j] = pk2(v.x, v.y); }
    }

    int e0 = blockIdx.x * 512 + t;
    int eA = e0, eB = e0 + 256;
    int ecA = (eA < E) ? eA : 0;
    int ecB = (eB < E) ? eB : 0;

    int srcA = ei[ecA],     srcB = ei[ecB];
    int tgtA = ei[E + ecA], tgtB = ei[E + ecB];
    int bbA  = be[ecA],     bbB  = be[ecB];

    u64 accA[5], accB[5];
    gather_base(srcA, tgtA, bbA, accA);
    gather_base(srcB, tgtB, bbB, accB);

    float aA[10], aB[10];
    load_ea(ea, ecA, aA);
    load_ea(ea, ecB, aB);

    // GEMM1: acc += ea @ W1c  (packed, weights shared across both edges)
#pragma unroll
    for (int k = 0; k < 10; k++) {
        ulonglong2 w01 = *(const ulonglong2*)&sW1c[k][0];
        ulonglong2 w23 = *(const ulonglong2*)&sW1c[k][4];
        u64        w4  = *(const u64*)&sW1c[k][8];
        u64 dA = pk2(aA[k], aA[k]);
        u64 dB = pk2(aB[k], aB[k]);
        accA[0] = fma2(dA, w01.x, accA[0]);
        accA[1] = fma2(dA, w01.y, accA[1]);
        accA[2] = fma2(dA, w23.x, accA[2]);
        accA[3] = fma2(dA, w23.y, accA[3]);
        accA[4] = fma2(dA, w4,    accA[4]);
        accB[0] = fma2(dB, w01.x, accB[0]);
        accB[1] = fma2(dB, w01.y, accB[1]);
        accB[2] = fma2(dB, w23.x, accB[2]);
        accB[3] = fma2(dB, w23.y, accB[3]);
        accB[4] = fma2(dB, w4,    accB[4]);
    }

    // leaky_relu(z) = max(z, 0.1z)
    float mA[10], mB[10];
#pragma unroll
    for (int j = 0; j < 5; j++) {
        float z0, z1;
        upk2(accA[j], z0, z1);
        mA[2 * j]     = fmaxf(z0, 0.1f * z0);
        mA[2 * j + 1] = fmaxf(z1, 0.1f * z1);
        upk2(accB[j], z0, z1);
        mB[2 * j]     = fmaxf(z0, 0.1f * z0);
        mB[2 * j + 1] = fmaxf(z1, 0.1f * z1);
    }

    // GEMM2: out = mid @ W2 + b2
    u64 oA[5], oB[5];
#pragma unroll
    for (int j = 0; j < 5; j++) { oA[j] = b2p[j]; oB[j] = b2p[j]; }
#pragma unroll
    for (int k = 0; k < 10; k++) {
        ulonglong2 w01 = *(const ulonglong2*)&sW2s[k][0];
        ulonglong2 w23 = *(const ulonglong2*)&sW2s[k][4];
        u64        w4  = *(const u64*)&sW2s[k][8];
        u64 dA = pk2(mA[k], mA[k]);
        u64 dB = pk2(mB[k], mB[k]);
        oA[0] = fma2(dA, w01.x, oA[0]);
        oA[1] = fma2(dA, w01.y, oA[1]);
        oA[2] = fma2(dA, w23.x, oA[2]);
        oA[3] = fma2(dA, w23.y, oA[3]);
        oA[4] = fma2(dA, w4,    oA[4]);
        oB[0] = fma2(dB, w01.x, oB[0]);
        oB[1] = fma2(dB, w01.y, oB[1]);
        oB[2] = fma2(dB, w23.x, oB[2]);
        oB[3] = fma2(dB, w23.y, oB[3]);
        oB[4] = fma2(dB, w4,    oB[4]);
    }

    if (eA < E) {
        float2* O = (float2*)(out + (size_t)eA * 10);
#pragma unroll
        for (int j = 0; j < 5; j++) { float2 v; upk2(oA[j], v.x, v.y); O[j] = v; }
    }
    if (eB < E) {
        float2* O = (float2*)(out + (size_t)eB * 10);
#pragma unroll
        for (int j = 0; j < 5; j++) { float2 v; upk2(oB[j], v.x, v.y); O[j] = v; }
    }
}

// ---------------------------------------------------------------------------
// Launch. Inputs (metadata order):
//  0 x_s[N_S,10] f32   1 x_t[N_T,5] f32   2 edge_index[2,E] i32
//  3 edge_attr[E,10] f32   4 u[B,10] f32   5 batch_e[E] i32
//  6 W1[35,10] f32   7 b1[10] f32   8 W2[10,10] f32   9 b2[10] f32
// ---------------------------------------------------------------------------
extern "C" void kernel_launch(void* const* d_in, const int* in_sizes, int n_in,
                              void* d_out, int out_size)
{
    const float* x_s = (const float*)d_in[0];
    const float* x_t = (const float*)d_in[1];
    const int*   ei  = (const int*)  d_in[2];
    const float* ea  = (const float*)d_in[3];
    const float* u   = (const float*)d_in[4];
    const int*   be  = (const int*)  d_in[5];
    const float* W1  = (const float*)d_in[6];
    const float* b1  = (const float*)d_in[7];
    const float* W2  = (const float*)d_in[8];
    const float* b2  = (const float*)d_in[9];
    float* out = (float*)d_out;

    int NS = in_sizes[0] / 10;
    int NT = in_sizes[1] / 5;
    int B  = in_sizes[4] / 10;
    int E  = in_sizes[5];
    if (NS > NS_MAX) NS = NS_MAX;
    if (NT > NT_MAX) NT = NT_MAX;
    if (B  > BB_MAX) B  = BB_MAX;

    // Precompute projections (W1 rows: x_s 0-9, x_t 10-14, edge_attr 15-24, u 25-34).
    proj_kernel<<<(NS + 255) / 256, 256>>>(x_s, NS, 10, W1, 0,  nullptr, 0);
    proj_kernel<<<(NT + 255) / 256, 256>>>(x_t, NT, 5,  W1, 10, nullptr, 1);
    proj_kernel<<<(B  + 255) / 256, 256>>>(u,   B,  10, W1, 25, b1,      2);

    // Fused edge MLP: 2 edges per thread, 512 edges per block.
    int grid = (E + 511) / 512;
    edge_kernel<<<grid, 256>>>(ei, ea, be, W1, W2, b2, out, E);
}